// round 9
// baseline (speedup 1.0000x reference)
#include <cuda_runtime.h>
#include <cuda_bf16.h>
#include <stdint.h>
#include <math.h>

#define NB  8192
#define HID 2048
#define CD  256
#define KC  4096

// ---------------- static scratch (allocation-free) ----------------
__device__ __align__(128) __nv_bfloat16 g_hhi[(size_t)NB * HID];
__device__ __align__(128) __nv_bfloat16 g_hlo[(size_t)NB * HID];
__device__ __align__(128) __nv_bfloat16 g_vhi[(size_t)NB * HID];
__device__ __align__(128) __nv_bfloat16 g_Wmu_hi[(size_t)HID * HID];
__device__ __align__(128) __nv_bfloat16 g_Wmu_lo[(size_t)HID * HID];
__device__ __align__(128) __nv_bfloat16 g_Win_hi[(size_t)CD * KC];
__device__ __align__(128) __nv_bfloat16 g_Wout_hi[(size_t)3 * HID * CD];
__device__ __align__(128) __nv_bfloat16 g_chi[(size_t)NB * CD];

// ---------------- helpers ----------------
__device__ __forceinline__ uint32_t smem_u32(const void* p) {
    uint32_t a;
    asm("{ .reg .u64 t; cvta.to.shared.u64 t, %1; cvt.u32.u64 %0, t; }" : "=r"(a) : "l"(p));
    return a;
}
__device__ __forceinline__ float sigm(float x) { return 1.0f / (1.0f + expf(-x)); }

#define CPA16(s, g) asm volatile("cp.async.cg.shared.global [%0], [%1], 16;" :: "r"(s), "l"(g))
#define CPC()       asm volatile("cp.async.commit_group;")
#define CPW(n)      asm volatile("cp.async.wait_group %0;" :: "n"(n))

__device__ __forceinline__ void ldsm4(uint32_t* d, uint32_t a) {
    asm volatile("ldmatrix.sync.aligned.m8n8.x4.shared.b16 {%0,%1,%2,%3}, [%4];"
                 : "=r"(d[0]), "=r"(d[1]), "=r"(d[2]), "=r"(d[3]) : "r"(a));
}
__device__ __forceinline__ void mma_bf16(float* c, const uint32_t* a, uint32_t b0, uint32_t b1) {
    asm volatile("mma.sync.aligned.m16n8k16.row.col.f32.bf16.bf16.f32 "
                 "{%0,%1,%2,%3},{%4,%5,%6,%7},{%8,%9},{%0,%1,%2,%3};"
                 : "+f"(c[0]), "+f"(c[1]), "+f"(c[2]), "+f"(c[3])
                 : "r"(a[0]), "r"(a[1]), "r"(a[2]), "r"(a[3]), "r"(b0), "r"(b1));
}

// ---------------- fused conversions ----------------
__device__ __forceinline__ void conv_hilo4(const float* s, __nv_bfloat16* hi,
                                           __nv_bfloat16* lo, int i)
{
    float4 x = *(const float4*)(s + i);
    __nv_bfloat16 h0 = __float2bfloat16(x.x), h1 = __float2bfloat16(x.y);
    __nv_bfloat16 h2 = __float2bfloat16(x.z), h3 = __float2bfloat16(x.w);
    __nv_bfloat162* H = (__nv_bfloat162*)(hi + i);
    H[0] = __halves2bfloat162(h0, h1); H[1] = __halves2bfloat162(h2, h3);
    __nv_bfloat162* L = (__nv_bfloat162*)(lo + i);
    L[0] = __halves2bfloat162(__float2bfloat16(x.x - __bfloat162float(h0)),
                              __float2bfloat16(x.y - __bfloat162float(h1)));
    L[1] = __halves2bfloat162(__float2bfloat16(x.z - __bfloat162float(h2)),
                              __float2bfloat16(x.w - __bfloat162float(h3)));
}
__device__ __forceinline__ void conv_hi4(const float* s, __nv_bfloat16* hi, int i)
{
    float4 x = *(const float4*)(s + i);
    __nv_bfloat162* H = (__nv_bfloat162*)(hi + i);
    H[0] = __halves2bfloat162(__float2bfloat16(x.x), __float2bfloat16(x.y));
    H[1] = __halves2bfloat162(__float2bfloat16(x.z), __float2bfloat16(x.w));
}

// conv A: h (hi/lo), v (hi), W_mu (hi/lo)
__global__ __launch_bounds__(256) void k_convA(const float* __restrict__ h,
                                               const float* __restrict__ v,
                                               const float* __restrict__ Wmu)
{
    const int NH = NB * HID, NW = HID * HID;
    int q = blockIdx.x * 256 + threadIdx.x;
    int i = q * 4;
    if (i < NH) { conv_hilo4(h, g_hhi, g_hlo, i); return; }
    i -= NH;
    if (i < NH) { conv_hi4(v, g_vhi, i); return; }
    i -= NH;
    if (i < NW) conv_hilo4(Wmu, g_Wmu_hi, g_Wmu_lo, i);
}
// conv B: W_in (hi), W_out (hi)
__global__ __launch_bounds__(256) void k_convB(const float* __restrict__ Win,
                                               const float* __restrict__ Wout)
{
    const int NI = CD * KC, NO = 3 * HID * CD;
    int i = (blockIdx.x * 256 + threadIdx.x) * 4;
    if (i < NI) { conv_hi4(Win, g_Win_hi, i); return; }
    i -= NI;
    if (i < NO) conv_hi4(Wout, g_Wout_hi, i);
}

// =============================================================================
// Geometry: block 128x128 (k1/k2), 8 warps 2(M)x4(N), warp tile 64x32;
// K stage 32; 80B-padded rows; non-trans ldmatrix both sides (K-contiguous).
// =============================================================================

#define COMPUTE_HL_128x128(As, Bs)                                             \
    _Pragma("unroll")                                                          \
    for (int kk = 0; kk < 32; kk += 16) {                                      \
        uint32_t ah[4][4], al[4][4];                                           \
        uint32_t aoff = (As) + wm * 5120 + (lane & 15) * 80 + (lane >> 4) * 16 + kk * 2; \
        _Pragma("unroll")                                                      \
        for (int mt = 0; mt < 4; mt++) {                                       \
            ldsm4(ah[mt], aoff + mt * 1280);                                   \
            ldsm4(al[mt], aoff + 10240 + mt * 1280);                           \
        }                                                                      \
        uint32_t boff = (Bs) + wn * 2560 + ((lane & 7) + ((lane >> 3) & 1) * 8) * 80 \
                        + (lane >> 4) * 16 + kk * 2;                           \
        _Pragma("unroll")                                                      \
        for (int np = 0; np < 2; np++) {                                       \
            uint32_t bh[4], bl[4];                                             \
            ldsm4(bh, boff + np * 1280);                                       \
            ldsm4(bl, boff + 10240 + np * 1280);                               \
            _Pragma("unroll")                                                  \
            for (int mt = 0; mt < 4; mt++) {                                   \
                mma_bf16(c[mt][np*2],   ah[mt], bh[0], bh[2]);                 \
                mma_bf16(c[mt][np*2+1], ah[mt], bh[1], bh[3]);                 \
                mma_bf16(c[mt][np*2],   ah[mt], bl[0], bl[2]);                 \
                mma_bf16(c[mt][np*2+1], ah[mt], bl[1], bl[3]);                 \
                mma_bf16(c[mt][np*2],   al[mt], bh[0], bh[2]);                 \
                mma_bf16(c[mt][np*2+1], al[mt], bh[1], bh[3]);                 \
            }                                                                  \
        }                                                                      \
    }

#define COMPUTE_SP_128x128(As, Bs)                                             \
    _Pragma("unroll")                                                          \
    for (int kk = 0; kk < 32; kk += 16) {                                      \
        uint32_t ah[4][4];                                                     \
        uint32_t aoff = (As) + wm * 5120 + (lane & 15) * 80 + (lane >> 4) * 16 + kk * 2; \
        _Pragma("unroll")                                                      \
        for (int mt = 0; mt < 4; mt++) ldsm4(ah[mt], aoff + mt * 1280);        \
        uint32_t boff = (Bs) + wn * 2560 + ((lane & 7) + ((lane >> 3) & 1) * 8) * 80 \
                        + (lane >> 4) * 16 + kk * 2;                           \
        _Pragma("unroll")                                                      \
        for (int np = 0; np < 2; np++) {                                       \
            uint32_t bh[4];                                                    \
            ldsm4(bh, boff + np * 1280);                                       \
            _Pragma("unroll")                                                  \
            for (int mt = 0; mt < 4; mt++) {                                   \
                mma_bf16(c[mt][np*2],   ah[mt], bh[0], bh[2]);                 \
                mma_bf16(c[mt][np*2+1], ah[mt], bh[1], bh[3]);                 \
            }                                                                  \
        }                                                                      \
    }

// ---------------- k1: ctrl = silu([h|v] @ W_in^T + b_in), single-pass -------
// 4-stage pipeline, lookahead 2, ONE sync per stage.
__global__ __launch_bounds__(256, 1) void k1_mma(const float* __restrict__ b_in)
{
    extern __shared__ char smem[];
    const int t = threadIdx.x, lane = t & 31, wid = t >> 5;
    const int wm = wid >> 2, wn = wid & 3;
    const int m0 = blockIdx.y * 128, n0 = blockIdx.x * 128;
    uint32_t sb = smem_u32(smem);
    float c[4][4][4] = {};

    auto load_stage = [&](int i, int buf) {
        int k0 = i * 32;
        const __nv_bfloat16* ah; int kc;
        if (k0 < HID) { ah = g_hhi; kc = k0; } else { ah = g_vhi; kc = k0 - HID; }
        uint32_t dst = sb + buf * 20480;
        #pragma unroll
        for (int it = 0; it < 4; it++) {
            int idx = t + it * 256;
            const __nv_bfloat16* gp;
            uint32_t s;
            if (idx < 512) {
                int row = idx >> 2, seg = idx & 3;
                gp = ah + (size_t)(m0 + row) * HID + kc + seg * 8;
                s = dst + row * 80 + seg * 16;
            } else {
                int j = idx - 512, row = j >> 2, seg = j & 3;
                gp = g_Win_hi + (size_t)(n0 + row) * KC + k0 + seg * 8;
                s = dst + 10240 + row * 80 + seg * 16;
            }
            CPA16(s, gp);
        }
        CPC();
    };

    const int NS = KC / 32;
    load_stage(0, 0); load_stage(1, 1);
    for (int i = 0; i < NS; i++) {
        if (i + 2 < NS) load_stage(i + 2, (i + 2) & 3); else CPC();
        CPW(2);
        __syncthreads();
        uint32_t As = sb + (i & 3) * 20480, Bs = As + 10240;
        COMPUTE_SP_128x128(As, Bs);
    }

    const int gr = lane >> 2, gc = (lane & 3) * 2;
    #pragma unroll
    for (int mt = 0; mt < 4; mt++)
        #pragma unroll
        for (int half = 0; half < 2; half++) {
            int row = m0 + wm * 64 + mt * 16 + gr + half * 8;
            #pragma unroll
            for (int nt = 0; nt < 4; nt++) {
                int ng = n0 + wn * 32 + nt * 8 + gc;
                float s0 = c[mt][nt][half * 2]     + b_in[ng];
                float s1 = c[mt][nt][half * 2 + 1] + b_in[ng + 1];
                s0 = s0 * sigm(s0); s1 = s1 * sigm(s1);
                *(__nv_bfloat162*)(g_chi + (size_t)row * CD + ng) =
                    __halves2bfloat162(__float2bfloat16(s0), __float2bfloat16(s1));
            }
        }
}

// ---------------- k2: mu_out = mu + h @ W_mu^T (3-pass hi/lo) ---------------
// 2-stage pipeline x 2 CTAs/SM: cross-CTA overlap fills sync/load bubbles.
__global__ __launch_bounds__(256, 2) void k2_mma(const float* __restrict__ mu,
                                                 float* __restrict__ mu_out)
{
    extern __shared__ char smem[];
    const int t = threadIdx.x, lane = t & 31, wid = t >> 5;
    const int wm = wid >> 2, wn = wid & 3;
    const int m0 = blockIdx.y * 128, n0 = blockIdx.x * 128;
    uint32_t sb = smem_u32(smem);
    float c[4][4][4] = {};

    auto load_stage = [&](int i, int buf) {
        int k0 = i * 32;
        uint32_t dst = sb + buf * 40960;
        #pragma unroll
        for (int it = 0; it < 8; it++) {
            int idx = t + it * 256;
            int region = idx >> 10, part = (idx >> 9) & 1;
            int row = (idx >> 2) & 127, seg = idx & 3;
            const __nv_bfloat16* gp;
            uint32_t s;
            if (region == 0) {
                gp = (part ? g_hlo : g_hhi) + (size_t)(m0 + row) * HID + k0 + seg * 8;
                s = dst + part * 10240 + row * 80 + seg * 16;
            } else {
                gp = (part ? g_Wmu_lo : g_Wmu_hi) + (size_t)(n0 + row) * HID + k0 + seg * 8;
                s = dst + 20480 + part * 10240 + row * 80 + seg * 16;
            }
            CPA16(s, gp);
        }
        CPC();
    };

    const int NS = HID / 32;
    load_stage(0, 0);
    for (int i = 0; i < NS; i++) {
        int buf = i & 1;
        if (i + 1 < NS) load_stage(i + 1, buf ^ 1); else CPC();
        CPW(1);
        __syncthreads();
        uint32_t As = sb + buf * 40960, Bs = As + 20480;
        COMPUTE_HL_128x128(As, Bs);
        __syncthreads();
    }

    const int gr = lane >> 2, gc = (lane & 3) * 2;
    #pragma unroll
    for (int mt = 0; mt < 4; mt++)
        #pragma unroll
        for (int half = 0; half < 2; half++) {
            int row = m0 + wm * 64 + mt * 16 + gr + half * 8;
            #pragma unroll
            for (int nt = 0; nt < 4; nt++) {
                int ng = n0 + wn * 32 + nt * 8 + gc;
                float2 o;
                o.x = c[mt][nt][half * 2]     + mu[ng];
                o.y = c[mt][nt][half * 2 + 1] + mu[ng + 1];
                *(float2*)(mu_out + (size_t)row * HID + ng) = o;
            }
        }
}

// ---------------- k3: 3-gate GEMM (K=256, single-pass) + dynamics epilogue --
// 4-stage pipeline, lookahead 2, ONE sync per stage.
__global__ __launch_bounds__(256, 1) void k3_mma(
    const float* __restrict__ h, const float* __restrict__ v,
    const float* __restrict__ b_out, const float* __restrict__ mu_out,
    float* __restrict__ h_next, float* __restrict__ v_next)
{
    extern __shared__ char smem[];
    const int t = threadIdx.x, lane = t & 31, wid = t >> 5;
    const int wm = wid >> 2, wn = wid & 3;
    const int m0 = blockIdx.y * 128, n0 = blockIdx.x * 64;
    uint32_t sb = smem_u32(smem);
    float c[3][4][2][4] = {};

    auto load_stage = [&](int i, int buf) {
        int k0 = i * 32;
        uint32_t dst = sb + buf * 25600;
        #pragma unroll
        for (int it = 0; it < 5; it++) {
            int idx = t + it * 256;
            const __nv_bfloat16* gp;
            uint32_t s;
            if (idx < 512) {
                int row = idx >> 2, seg = idx & 3;
                gp = g_chi + (size_t)(m0 + row) * CD + k0 + seg * 8;
                s = dst + row * 80 + seg * 16;
            } else {
                int j = idx - 512, row = j >> 2, seg = j & 3;
                int g = row >> 6, rg = row & 63;
                gp = g_Wout_hi + (size_t)(g * HID + n0 + rg) * CD + k0 + seg * 8;
                s = dst + 10240 + g * 5120 + rg * 80 + seg * 16;
            }
            CPA16(s, gp);
        }
        CPC();
    };

    const int NS = CD / 32;  // 8
    load_stage(0, 0); load_stage(1, 1);
    for (int i = 0; i < NS; i++) {
        if (i + 2 < NS) load_stage(i + 2, (i + 2) & 3); else CPC();
        CPW(2);
        __syncthreads();
        uint32_t As = sb + (i & 3) * 25600, Bs = As + 10240;
        #pragma unroll
        for (int kk = 0; kk < 32; kk += 16) {
            uint32_t ah[4][4];
            uint32_t aoff = As + wm * 5120 + (lane & 15) * 80 + (lane >> 4) * 16 + kk * 2;
            #pragma unroll
            for (int mt = 0; mt < 4; mt++) ldsm4(ah[mt], aoff + mt * 1280);
            uint32_t boff = Bs + wn * 1280 + ((lane & 7) + ((lane >> 3) & 1) * 8) * 80
                            + (lane >> 4) * 16 + kk * 2;
            #pragma unroll
            for (int g = 0; g < 3; g++) {
                uint32_t bh[4];
                ldsm4(bh, boff + g * 5120);
                #pragma unroll
                for (int mt = 0; mt < 4; mt++) {
                    mma_bf16(c[g][mt][0], ah[mt], bh[0], bh[2]);
                    mma_bf16(c[g][mt][1], ah[mt], bh[1], bh[3]);
                }
            }
        }
    }

    const int gr = lane >> 2, gc = (lane & 3) * 2;
    #pragma unroll
    for (int mt = 0; mt < 4; mt++)
        #pragma unroll
        for (int half = 0; half < 2; half++) {
            int row = m0 + wm * 64 + mt * 16 + gr + half * 8;
            size_t rb = (size_t)row * HID;
            #pragma unroll
            for (int nt = 0; nt < 2; nt++) {
                int ng = n0 + wn * 16 + nt * 8 + gc;
                size_t o = rb + ng;
                float a0 = c[0][mt][nt][half*2]   + b_out[ng];
                float a1 = c[0][mt][nt][half*2+1] + b_out[ng + 1];
                float b0 = c[1][mt][nt][half*2]   + b_out[HID + ng];
                float b1 = c[1][mt][nt][half*2+1] + b_out[HID + ng + 1];
                float g0 = c[2][mt][nt][half*2]   + b_out[2 * HID + ng];
                float g1 = c[2][mt][nt][half*2+1] + b_out[2 * HID + ng + 1];
                float al0 = sigm(a0), al1 = sigm(a1);
                float be0 = fminf(fmaxf(b0, 0.f) + log1pf(expf(-fabsf(b0))), 2.0f);
                float be1 = fminf(fmaxf(b1, 0.f) + log1pf(expf(-fabsf(b1))), 2.0f);
                float gt0 = sigm(g0), gt1 = sigm(g1);
                float2 hv = *(const float2*)(h + o);
                float2 vv = *(const float2*)(v + o);
                float2 mc = *(const float2*)(mu_out + o);
                float vn0 = al0 * vv.x - be0 * (hv.x - mc.x);
                float vn1 = al1 * vv.y - be1 * (hv.y - mc.y);
                vn0 = fminf(fmaxf(vn0, -10.f), 10.f);
                vn1 = fminf(fmaxf(vn1, -10.f), 10.f);
                float2 hn = { hv.x + 0.1f * gt0 * vn0, hv.y + 0.1f * gt1 * vn1 };
                float2 vn = { vn0, vn1 };
                *(float2*)(h_next + o) = hn;
                *(float2*)(v_next + o) = vn;
            }
        }
}

// ---------------- launch ----------------
extern "C" void kernel_launch(void* const* d_in, const int* in_sizes, int n_in,
                              void* d_out, int out_size)
{
    const float* h     = (const float*)d_in[0];
    const float* v     = (const float*)d_in[1];
    const float* W_in  = (const float*)d_in[2];
    const float* b_in  = (const float*)d_in[3];
    const float* W_out = (const float*)d_in[4];
    const float* b_out = (const float*)d_in[5];
    const float* W_mu  = (const float*)d_in[6];
    const float* mu    = (const float*)d_in[7];

    float* out    = (float*)d_out;
    float* h_next = out;
    float* v_next = out + (size_t)NB * HID;
    float* mu_out = out + 2 * (size_t)NB * HID;

    cudaFuncSetAttribute(k1_mma, cudaFuncAttributeMaxDynamicSharedMemorySize, 4 * 20480);
    cudaFuncSetAttribute(k2_mma, cudaFuncAttributeMaxDynamicSharedMemorySize, 2 * 40960);
    cudaFuncSetAttribute(k3_mma, cudaFuncAttributeMaxDynamicSharedMemorySize, 4 * 25600);

    // conv A: h(hi/lo) + v(hi) + Wmu(hi/lo)
    const int qa = (2 * NB * HID + HID * HID) / 4;
    k_convA<<<qa / 256, 256>>>(h, v, W_mu);
    // conv B: Win(hi) + Wout(hi)
    const int qb = (CD * KC + 3 * HID * CD) / 4;
    k_convB<<<qb / 256, 256>>>(W_in, W_out);

    k1_mma<<<dim3(CD / 128,  NB / 128), 256, 4 * 20480>>>(b_in);
    k2_mma<<<dim3(HID / 128, NB / 128), 256, 2 * 40960>>>(mu, mu_out);   // 4th launch -> profiled
    k3_mma<<<dim3(HID / 64,  NB / 128), 256, 4 * 25600>>>(h, v, b_out, mu_out,
                                                          h_next, v_next);
}

// round 10
// speedup vs baseline: 2.4657x; 2.4657x over previous
#include <cuda_runtime.h>
#include <cuda_fp16.h>
#include <stdint.h>
#include <math.h>

#define NB  8192
#define HID 2048
#define CD  256
#define KC  4096

// ---------------- static scratch (allocation-free), all fp16 ----------------
__device__ __align__(128) __half g_h16[(size_t)NB * HID];
__device__ __align__(128) __half g_v16[(size_t)NB * HID];
__device__ __align__(128) __half g_Wmu16[(size_t)HID * HID];
__device__ __align__(128) __half g_Win16[(size_t)CD * KC];
__device__ __align__(128) __half g_Wout16[(size_t)3 * HID * CD];
__device__ __align__(128) __half g_c16[(size_t)NB * CD];

// ---------------- helpers ----------------
__device__ __forceinline__ uint32_t smem_u32(const void* p) {
    uint32_t a;
    asm("{ .reg .u64 t; cvta.to.shared.u64 t, %1; cvt.u32.u64 %0, t; }" : "=r"(a) : "l"(p));
    return a;
}
__device__ __forceinline__ float sigm(float x) { return 1.0f / (1.0f + expf(-x)); }

#define CPA16(s, g) asm volatile("cp.async.cg.shared.global [%0], [%1], 16;" :: "r"(s), "l"(g))
#define CPC()       asm volatile("cp.async.commit_group;")
#define CPW(n)      asm volatile("cp.async.wait_group %0;" :: "n"(n))

__device__ __forceinline__ void ldsm4(uint32_t* d, uint32_t a) {
    asm volatile("ldmatrix.sync.aligned.m8n8.x4.shared.b16 {%0,%1,%2,%3}, [%4];"
                 : "=r"(d[0]), "=r"(d[1]), "=r"(d[2]), "=r"(d[3]) : "r"(a));
}
__device__ __forceinline__ void mma_f16(float* c, const uint32_t* a, uint32_t b0, uint32_t b1) {
    asm volatile("mma.sync.aligned.m16n8k16.row.col.f32.f16.f16.f32 "
                 "{%0,%1,%2,%3},{%4,%5,%6,%7},{%8,%9},{%0,%1,%2,%3};"
                 : "+f"(c[0]), "+f"(c[1]), "+f"(c[2]), "+f"(c[3])
                 : "r"(a[0]), "r"(a[1]), "r"(a[2]), "r"(a[3]), "r"(b0), "r"(b1));
}

// ---------------- fp32 -> fp16 conversions ----------------
__device__ __forceinline__ void conv4(const float* s, __half* d, int i)
{
    float4 x = *(const float4*)(s + i);
    __half2* D = (__half2*)(d + i);
    D[0] = __floats2half2_rn(x.x, x.y);
    D[1] = __floats2half2_rn(x.z, x.w);
}
// conv A: h, v, W_mu
__global__ __launch_bounds__(256) void k_convA(const float* __restrict__ h,
                                               const float* __restrict__ v,
                                               const float* __restrict__ Wmu)
{
    const int NH = NB * HID, NW = HID * HID;
    int i = (blockIdx.x * 256 + threadIdx.x) * 4;
    if (i < NH) { conv4(h, g_h16, i); return; }
    i -= NH;
    if (i < NH) { conv4(v, g_v16, i); return; }
    i -= NH;
    if (i < NW) conv4(Wmu, g_Wmu16, i);
}
// conv B: W_in, W_out
__global__ __launch_bounds__(256) void k_convB(const float* __restrict__ Win,
                                               const float* __restrict__ Wout)
{
    const int NI = CD * KC, NO = 3 * HID * CD;
    int i = (blockIdx.x * 256 + threadIdx.x) * 4;
    if (i < NI) { conv4(Win, g_Win16, i); return; }
    i -= NI;
    if (i < NO) conv4(Wout, g_Wout16, i);
}

// =============================================================================
// Geometry: block 128x128 (k1/k2), 8 warps 2(M)x4(N), warp tile 64x32;
// K stage 32; 80B-padded rows; non-trans ldmatrix both sides (K-contiguous).
// Single-pass fp16, 4-stage cp.async pipeline, lookahead 2, one sync/stage.
// =============================================================================

#define COMPUTE_SP_128x128(As, Bs)                                             \
    _Pragma("unroll")                                                          \
    for (int kk = 0; kk < 32; kk += 16) {                                      \
        uint32_t ah[4][4];                                                     \
        uint32_t aoff = (As) + wm * 5120 + (lane & 15) * 80 + (lane >> 4) * 16 + kk * 2; \
        _Pragma("unroll")                                                      \
        for (int mt = 0; mt < 4; mt++) ldsm4(ah[mt], aoff + mt * 1280);        \
        uint32_t boff = (Bs) + wn * 2560 + ((lane & 7) + ((lane >> 3) & 1) * 8) * 80 \
                        + (lane >> 4) * 16 + kk * 2;                           \
        _Pragma("unroll")                                                      \
        for (int np = 0; np < 2; np++) {                                       \
            uint32_t bh[4];                                                    \
            ldsm4(bh, boff + np * 1280);                                       \
            _Pragma("unroll")                                                  \
            for (int mt = 0; mt < 4; mt++) {                                   \
                mma_f16(c[mt][np*2],   ah[mt], bh[0], bh[2]);                  \
                mma_f16(c[mt][np*2+1], ah[mt], bh[1], bh[3]);                  \
            }                                                                  \
        }                                                                      \
    }

// ---------------- k1: ctrl = silu([h|v] @ W_in^T + b_in) --------------------
__global__ __launch_bounds__(256, 1) void k1_mma(const float* __restrict__ b_in)
{
    extern __shared__ char smem[];
    const int t = threadIdx.x, lane = t & 31, wid = t >> 5;
    const int wm = wid >> 2, wn = wid & 3;
    const int m0 = blockIdx.y * 128, n0 = blockIdx.x * 128;
    uint32_t sb = smem_u32(smem);
    float c[4][4][4] = {};

    auto load_stage = [&](int i, int buf) {
        int k0 = i * 32;
        const __half* ah; int kc;
        if (k0 < HID) { ah = g_h16; kc = k0; } else { ah = g_v16; kc = k0 - HID; }
        uint32_t dst = sb + buf * 20480;
        #pragma unroll
        for (int it = 0; it < 4; it++) {
            int idx = t + it * 256;
            const __half* gp;
            uint32_t s;
            if (idx < 512) {
                int row = idx >> 2, seg = idx & 3;
                gp = ah + (size_t)(m0 + row) * HID + kc + seg * 8;
                s = dst + row * 80 + seg * 16;
            } else {
                int j = idx - 512, row = j >> 2, seg = j & 3;
                gp = g_Win16 + (size_t)(n0 + row) * KC + k0 + seg * 8;
                s = dst + 10240 + row * 80 + seg * 16;
            }
            CPA16(s, gp);
        }
        CPC();
    };

    const int NS = KC / 32;
    load_stage(0, 0); load_stage(1, 1);
    for (int i = 0; i < NS; i++) {
        if (i + 2 < NS) load_stage(i + 2, (i + 2) & 3); else CPC();
        CPW(2);
        __syncthreads();
        uint32_t As = sb + (i & 3) * 20480, Bs = As + 10240;
        COMPUTE_SP_128x128(As, Bs);
    }

    const int gr = lane >> 2, gc = (lane & 3) * 2;
    #pragma unroll
    for (int mt = 0; mt < 4; mt++)
        #pragma unroll
        for (int half = 0; half < 2; half++) {
            int row = m0 + wm * 64 + mt * 16 + gr + half * 8;
            #pragma unroll
            for (int nt = 0; nt < 4; nt++) {
                int ng = n0 + wn * 32 + nt * 8 + gc;
                float s0 = c[mt][nt][half * 2]     + b_in[ng];
                float s1 = c[mt][nt][half * 2 + 1] + b_in[ng + 1];
                s0 = s0 * sigm(s0); s1 = s1 * sigm(s1);
                *(__half2*)(g_c16 + (size_t)row * CD + ng) = __floats2half2_rn(s0, s1);
            }
        }
}

// ---------------- k2: mu_out = mu + h @ W_mu^T (single-pass fp16) -----------
__global__ __launch_bounds__(256, 1) void k2_mma(const float* __restrict__ mu,
                                                 float* __restrict__ mu_out)
{
    extern __shared__ char smem[];
    const int t = threadIdx.x, lane = t & 31, wid = t >> 5;
    const int wm = wid >> 2, wn = wid & 3;
    const int m0 = blockIdx.y * 128, n0 = blockIdx.x * 128;
    uint32_t sb = smem_u32(smem);
    float c[4][4][4] = {};

    auto load_stage = [&](int i, int buf) {
        int k0 = i * 32;
        uint32_t dst = sb + buf * 20480;
        #pragma unroll
        for (int it = 0; it < 4; it++) {
            int idx = t + it * 256;
            const __half* gp;
            uint32_t s;
            if (idx < 512) {
                int row = idx >> 2, seg = idx & 3;
                gp = g_h16 + (size_t)(m0 + row) * HID + k0 + seg * 8;
                s = dst + row * 80 + seg * 16;
            } else {
                int j = idx - 512, row = j >> 2, seg = j & 3;
                gp = g_Wmu16 + (size_t)(n0 + row) * HID + k0 + seg * 8;
                s = dst + 10240 + row * 80 + seg * 16;
            }
            CPA16(s, gp);
        }
        CPC();
    };

    const int NS = HID / 32;
    load_stage(0, 0); load_stage(1, 1);
    for (int i = 0; i < NS; i++) {
        if (i + 2 < NS) load_stage(i + 2, (i + 2) & 3); else CPC();
        CPW(2);
        __syncthreads();
        uint32_t As = sb + (i & 3) * 20480, Bs = As + 10240;
        COMPUTE_SP_128x128(As, Bs);
    }

    const int gr = lane >> 2, gc = (lane & 3) * 2;
    #pragma unroll
    for (int mt = 0; mt < 4; mt++)
        #pragma unroll
        for (int half = 0; half < 2; half++) {
            int row = m0 + wm * 64 + mt * 16 + gr + half * 8;
            #pragma unroll
            for (int nt = 0; nt < 4; nt++) {
                int ng = n0 + wn * 32 + nt * 8 + gc;
                float2 o;
                o.x = c[mt][nt][half * 2]     + mu[ng];
                o.y = c[mt][nt][half * 2 + 1] + mu[ng + 1];
                *(float2*)(mu_out + (size_t)row * HID + ng) = o;
            }
        }
}

// ---------------- k3: 3-gate GEMM (K=256) + fused dynamics epilogue ---------
__global__ __launch_bounds__(256, 1) void k3_mma(
    const float* __restrict__ h, const float* __restrict__ v,
    const float* __restrict__ b_out, const float* __restrict__ mu_out,
    float* __restrict__ h_next, float* __restrict__ v_next)
{
    extern __shared__ char smem[];
    const int t = threadIdx.x, lane = t & 31, wid = t >> 5;
    const int wm = wid >> 2, wn = wid & 3;
    const int m0 = blockIdx.y * 128, n0 = blockIdx.x * 64;
    uint32_t sb = smem_u32(smem);
    float c[3][4][2][4] = {};

    auto load_stage = [&](int i, int buf) {
        int k0 = i * 32;
        uint32_t dst = sb + buf * 25600;
        #pragma unroll
        for (int it = 0; it < 5; it++) {
            int idx = t + it * 256;
            const __half* gp;
            uint32_t s;
            if (idx < 512) {
                int row = idx >> 2, seg = idx & 3;
                gp = g_c16 + (size_t)(m0 + row) * CD + k0 + seg * 8;
                s = dst + row * 80 + seg * 16;
            } else {
                int j = idx - 512, row = j >> 2, seg = j & 3;
                int g = row >> 6, rg = row & 63;
                gp = g_Wout16 + (size_t)(g * HID + n0 + rg) * CD + k0 + seg * 8;
                s = dst + 10240 + g * 5120 + rg * 80 + seg * 16;
            }
            CPA16(s, gp);
        }
        CPC();
    };

    const int NS = CD / 32;  // 8
    load_stage(0, 0); load_stage(1, 1);
    for (int i = 0; i < NS; i++) {
        if (i + 2 < NS) load_stage(i + 2, (i + 2) & 3); else CPC();
        CPW(2);
        __syncthreads();
        uint32_t As = sb + (i & 3) * 25600, Bs = As + 10240;
        #pragma unroll
        for (int kk = 0; kk < 32; kk += 16) {
            uint32_t ah[4][4];
            uint32_t aoff = As + wm * 5120 + (lane & 15) * 80 + (lane >> 4) * 16 + kk * 2;
            #pragma unroll
            for (int mt = 0; mt < 4; mt++) ldsm4(ah[mt], aoff + mt * 1280);
            uint32_t boff = Bs + wn * 1280 + ((lane & 7) + ((lane >> 3) & 1) * 8) * 80
                            + (lane >> 4) * 16 + kk * 2;
            #pragma unroll
            for (int g = 0; g < 3; g++) {
                uint32_t bh[4];
                ldsm4(bh, boff + g * 5120);
                #pragma unroll
                for (int mt = 0; mt < 4; mt++) {
                    mma_f16(c[g][mt][0], ah[mt], bh[0], bh[2]);
                    mma_f16(c[g][mt][1], ah[mt], bh[1], bh[3]);
                }
            }
        }
    }

    const int gr = lane >> 2, gc = (lane & 3) * 2;
    #pragma unroll
    for (int mt = 0; mt < 4; mt++)
        #pragma unroll
        for (int half = 0; half < 2; half++) {
            int row = m0 + wm * 64 + mt * 16 + gr + half * 8;
            size_t rb = (size_t)row * HID;
            #pragma unroll
            for (int nt = 0; nt < 2; nt++) {
                int ng = n0 + wn * 16 + nt * 8 + gc;
                size_t o = rb + ng;
                float a0 = c[0][mt][nt][half*2]   + b_out[ng];
                float a1 = c[0][mt][nt][half*2+1] + b_out[ng + 1];
                float b0 = c[1][mt][nt][half*2]   + b_out[HID + ng];
                float b1 = c[1][mt][nt][half*2+1] + b_out[HID + ng + 1];
                float g0 = c[2][mt][nt][half*2]   + b_out[2 * HID + ng];
                float g1 = c[2][mt][nt][half*2+1] + b_out[2 * HID + ng + 1];
                float al0 = sigm(a0), al1 = sigm(a1);
                float be0 = fminf(fmaxf(b0, 0.f) + log1pf(expf(-fabsf(b0))), 2.0f);
                float be1 = fminf(fmaxf(b1, 0.f) + log1pf(expf(-fabsf(b1))), 2.0f);
                float gt0 = sigm(g0), gt1 = sigm(g1);
                float2 hv = *(const float2*)(h + o);
                float2 vv = *(const float2*)(v + o);
                float2 mc = *(const float2*)(mu_out + o);
                float vn0 = al0 * vv.x - be0 * (hv.x - mc.x);
                float vn1 = al1 * vv.y - be1 * (hv.y - mc.y);
                vn0 = fminf(fmaxf(vn0, -10.f), 10.f);
                vn1 = fminf(fmaxf(vn1, -10.f), 10.f);
                float2 hn = { hv.x + 0.1f * gt0 * vn0, hv.y + 0.1f * gt1 * vn1 };
                float2 vn = { vn0, vn1 };
                *(float2*)(h_next + o) = hn;
                *(float2*)(v_next + o) = vn;
            }
        }
}

// ---------------- launch ----------------
extern "C" void kernel_launch(void* const* d_in, const int* in_sizes, int n_in,
                              void* d_out, int out_size)
{
    const float* h     = (const float*)d_in[0];
    const float* v     = (const float*)d_in[1];
    const float* W_in  = (const float*)d_in[2];
    const float* b_in  = (const float*)d_in[3];
    const float* W_out = (const float*)d_in[4];
    const float* b_out = (const float*)d_in[5];
    const float* W_mu  = (const float*)d_in[6];
    const float* mu    = (const float*)d_in[7];

    float* out    = (float*)d_out;
    float* h_next = out;
    float* v_next = out + (size_t)NB * HID;
    float* mu_out = out + 2 * (size_t)NB * HID;

    cudaFuncSetAttribute(k1_mma, cudaFuncAttributeMaxDynamicSharedMemorySize, 4 * 20480);
    cudaFuncSetAttribute(k2_mma, cudaFuncAttributeMaxDynamicSharedMemorySize, 4 * 20480);
    cudaFuncSetAttribute(k3_mma, cudaFuncAttributeMaxDynamicSharedMemorySize, 4 * 25600);

    const int qa = (2 * NB * HID + HID * HID) / 4;
    k_convA<<<qa / 256, 256>>>(h, v, W_mu);
    const int qb = (CD * KC + 3 * HID * CD) / 4;
    k_convB<<<qb / 256, 256>>>(W_in, W_out);

    k1_mma<<<dim3(CD / 128,  NB / 128), 256, 4 * 20480>>>(b_in);
    k2_mma<<<dim3(HID / 128, NB / 128), 256, 4 * 20480>>>(mu, mu_out);   // 4th launch -> profiled
    k3_mma<<<dim3(HID / 64,  NB / 128), 256, 4 * 25600>>>(h, v, b_out, mu_out,
                                                          h_next, v_next);
}

// round 11
// speedup vs baseline: 2.4659x; 1.0001x over previous
#include <cuda_runtime.h>
#include <cuda_fp16.h>
#include <stdint.h>
#include <math.h>

#define NB  8192
#define HID 2048
#define CD  256
#define KC  4096

// ---------------- static scratch (allocation-free), all fp16 ----------------
__device__ __align__(128) __half g_h16[(size_t)NB * HID];
__device__ __align__(128) __half g_v16[(size_t)NB * HID];
__device__ __align__(128) __half g_Wmu16[(size_t)HID * HID];
__device__ __align__(128) __half g_Win16[(size_t)CD * KC];
__device__ __align__(128) __half g_Wout16[(size_t)3 * HID * CD];
__device__ __align__(128) __half g_c16[(size_t)NB * CD];

// ---------------- helpers ----------------
__device__ __forceinline__ uint32_t smem_u32(const void* p) {
    uint32_t a;
    asm("{ .reg .u64 t; cvta.to.shared.u64 t, %1; cvt.u32.u64 %0, t; }" : "=r"(a) : "l"(p));
    return a;
}
__device__ __forceinline__ float sigm(float x) { return 1.0f / (1.0f + expf(-x)); }

#define CPA16(s, g) asm volatile("cp.async.cg.shared.global [%0], [%1], 16;" :: "r"(s), "l"(g))
#define CPC()       asm volatile("cp.async.commit_group;")
#define CPW(n)      asm volatile("cp.async.wait_group %0;" :: "n"(n))

__device__ __forceinline__ void ldsm4(uint32_t* d, uint32_t a) {
    asm volatile("ldmatrix.sync.aligned.m8n8.x4.shared.b16 {%0,%1,%2,%3}, [%4];"
                 : "=r"(d[0]), "=r"(d[1]), "=r"(d[2]), "=r"(d[3]) : "r"(a));
}
__device__ __forceinline__ void mma_f16(float* c, const uint32_t* a, uint32_t b0, uint32_t b1) {
    asm volatile("mma.sync.aligned.m16n8k16.row.col.f32.f16.f16.f32 "
                 "{%0,%1,%2,%3},{%4,%5,%6,%7},{%8,%9},{%0,%1,%2,%3};"
                 : "+f"(c[0]), "+f"(c[1]), "+f"(c[2]), "+f"(c[3])
                 : "r"(a[0]), "r"(a[1]), "r"(a[2]), "r"(a[3]), "r"(b0), "r"(b1));
}

// ---------------- fp32 -> fp16 conversions ----------------
__device__ __forceinline__ void conv4(const float* s, __half* d, int i)
{
    float4 x = *(const float4*)(s + i);
    __half2* D = (__half2*)(d + i);
    D[0] = __floats2half2_rn(x.x, x.y);
    D[1] = __floats2half2_rn(x.z, x.w);
}
__global__ __launch_bounds__(256) void k_convA(const float* __restrict__ h,
                                               const float* __restrict__ v,
                                               const float* __restrict__ Wmu)
{
    const int NH = NB * HID, NW = HID * HID;
    int i = (blockIdx.x * 256 + threadIdx.x) * 4;
    if (i < NH) { conv4(h, g_h16, i); return; }
    i -= NH;
    if (i < NH) { conv4(v, g_v16, i); return; }
    i -= NH;
    if (i < NW) conv4(Wmu, g_Wmu16, i);
}
__global__ __launch_bounds__(256) void k_convB(const float* __restrict__ Win,
                                               const float* __restrict__ Wout)
{
    const int NI = CD * KC, NO = 3 * HID * CD;
    int i = (blockIdx.x * 256 + threadIdx.x) * 4;
    if (i < NI) { conv4(Win, g_Win16, i); return; }
    i -= NI;
    if (i < NO) conv4(Wout, g_Wout16, i);
}

// =============================================================================
// Geometry: block 128x128 (k1/k2), 8 warps 2(M)x4(N), warp tile 64x32;
// K stage 32; 80B-padded rows; non-trans ldmatrix both sides (K-contiguous).
// Single-pass fp16, 4-stage cp.async pipeline, lookahead 2, one sync/stage.
// NEW: k1/k2 run 2 CTAs/SM (fits: 106 regs < 128 clamp, 160KB smem < 228KB).
// =============================================================================

#define COMPUTE_SP_128x128(As, Bs)                                             \
    _Pragma("unroll")                                                          \
    for (int kk = 0; kk < 32; kk += 16) {                                      \
        uint32_t ah[4][4];                                                     \
        uint32_t aoff = (As) + wm * 5120 + (lane & 15) * 80 + (lane >> 4) * 16 + kk * 2; \
        _Pragma("unroll")                                                      \
        for (int mt = 0; mt < 4; mt++) ldsm4(ah[mt], aoff + mt * 1280);        \
        uint32_t boff = (Bs) + wn * 2560 + ((lane & 7) + ((lane >> 3) & 1) * 8) * 80 \
                        + (lane >> 4) * 16 + kk * 2;                           \
        _Pragma("unroll")                                                      \
        for (int np = 0; np < 2; np++) {                                       \
            uint32_t bh[4];                                                    \
            ldsm4(bh, boff + np * 1280);                                       \
            _Pragma("unroll")                                                  \
            for (int mt = 0; mt < 4; mt++) {                                   \
                mma_f16(c[mt][np*2],   ah[mt], bh[0], bh[2]);                  \
                mma_f16(c[mt][np*2+1], ah[mt], bh[1], bh[3]);                  \
            }                                                                  \
        }                                                                      \
    }

// ---------------- k1: ctrl = silu([h|v] @ W_in^T + b_in) --------------------
__global__ __launch_bounds__(256, 2) void k1_mma(const float* __restrict__ b_in)
{
    extern __shared__ char smem[];
    const int t = threadIdx.x, lane = t & 31, wid = t >> 5;
    const int wm = wid >> 2, wn = wid & 3;
    const int m0 = blockIdx.y * 128, n0 = blockIdx.x * 128;
    uint32_t sb = smem_u32(smem);
    float c[4][4][4] = {};

    auto load_stage = [&](int i, int buf) {
        int k0 = i * 32;
        const __half* ah; int kc;
        if (k0 < HID) { ah = g_h16; kc = k0; } else { ah = g_v16; kc = k0 - HID; }
        uint32_t dst = sb + buf * 20480;
        #pragma unroll
        for (int it = 0; it < 4; it++) {
            int idx = t + it * 256;
            const __half* gp;
            uint32_t s;
            if (idx < 512) {
                int row = idx >> 2, seg = idx & 3;
                gp = ah + (size_t)(m0 + row) * HID + kc + seg * 8;
                s = dst + row * 80 + seg * 16;
            } else {
                int j = idx - 512, row = j >> 2, seg = j & 3;
                gp = g_Win16 + (size_t)(n0 + row) * KC + k0 + seg * 8;
                s = dst + 10240 + row * 80 + seg * 16;
            }
            CPA16(s, gp);
        }
        CPC();
    };

    const int NS = KC / 32;
    load_stage(0, 0); load_stage(1, 1);
    for (int i = 0; i < NS; i++) {
        if (i + 2 < NS) load_stage(i + 2, (i + 2) & 3); else CPC();
        CPW(2);
        __syncthreads();
        uint32_t As = sb + (i & 3) * 20480, Bs = As + 10240;
        COMPUTE_SP_128x128(As, Bs);
    }

    const int gr = lane >> 2, gc = (lane & 3) * 2;
    #pragma unroll
    for (int mt = 0; mt < 4; mt++)
        #pragma unroll
        for (int half = 0; half < 2; half++) {
            int row = m0 + wm * 64 + mt * 16 + gr + half * 8;
            #pragma unroll
            for (int nt = 0; nt < 4; nt++) {
                int ng = n0 + wn * 32 + nt * 8 + gc;
                float s0 = c[mt][nt][half * 2]     + b_in[ng];
                float s1 = c[mt][nt][half * 2 + 1] + b_in[ng + 1];
                s0 = s0 * sigm(s0); s1 = s1 * sigm(s1);
                *(__half2*)(g_c16 + (size_t)row * CD + ng) = __floats2half2_rn(s0, s1);
            }
        }
}

// ---------------- k2: mu_out = mu + h @ W_mu^T (single-pass fp16) -----------
__global__ __launch_bounds__(256, 2) void k2_mma(const float* __restrict__ mu,
                                                 float* __restrict__ mu_out)
{
    extern __shared__ char smem[];
    const int t = threadIdx.x, lane = t & 31, wid = t >> 5;
    const int wm = wid >> 2, wn = wid & 3;
    const int m0 = blockIdx.y * 128, n0 = blockIdx.x * 128;
    uint32_t sb = smem_u32(smem);
    float c[4][4][4] = {};

    auto load_stage = [&](int i, int buf) {
        int k0 = i * 32;
        uint32_t dst = sb + buf * 20480;
        #pragma unroll
        for (int it = 0; it < 4; it++) {
            int idx = t + it * 256;
            const __half* gp;
            uint32_t s;
            if (idx < 512) {
                int row = idx >> 2, seg = idx & 3;
                gp = g_h16 + (size_t)(m0 + row) * HID + k0 + seg * 8;
                s = dst + row * 80 + seg * 16;
            } else {
                int j = idx - 512, row = j >> 2, seg = j & 3;
                gp = g_Wmu16 + (size_t)(n0 + row) * HID + k0 + seg * 8;
                s = dst + 10240 + row * 80 + seg * 16;
            }
            CPA16(s, gp);
        }
        CPC();
    };

    const int NS = HID / 32;
    load_stage(0, 0); load_stage(1, 1);
    for (int i = 0; i < NS; i++) {
        if (i + 2 < NS) load_stage(i + 2, (i + 2) & 3); else CPC();
        CPW(2);
        __syncthreads();
        uint32_t As = sb + (i & 3) * 20480, Bs = As + 10240;
        COMPUTE_SP_128x128(As, Bs);
    }

    const int gr = lane >> 2, gc = (lane & 3) * 2;
    #pragma unroll
    for (int mt = 0; mt < 4; mt++)
        #pragma unroll
        for (int half = 0; half < 2; half++) {
            int row = m0 + wm * 64 + mt * 16 + gr + half * 8;
            #pragma unroll
            for (int nt = 0; nt < 4; nt++) {
                int ng = n0 + wn * 32 + nt * 8 + gc;
                float2 o;
                o.x = c[mt][nt][half * 2]     + mu[ng];
                o.y = c[mt][nt][half * 2 + 1] + mu[ng + 1];
                *(float2*)(mu_out + (size_t)row * HID + ng) = o;
            }
        }
}

// ---------------- k3: 3-gate GEMM (K=256) + fused dynamics epilogue ---------
__global__ __launch_bounds__(256, 1) void k3_mma(
    const float* __restrict__ h, const float* __restrict__ v,
    const float* __restrict__ b_out, const float* __restrict__ mu_out,
    float* __restrict__ h_next, float* __restrict__ v_next)
{
    extern __shared__ char smem[];
    const int t = threadIdx.x, lane = t & 31, wid = t >> 5;
    const int wm = wid >> 2, wn = wid & 3;
    const int m0 = blockIdx.y * 128, n0 = blockIdx.x * 64;
    uint32_t sb = smem_u32(smem);
    float c[3][4][2][4] = {};

    auto load_stage = [&](int i, int buf) {
        int k0 = i * 32;
        uint32_t dst = sb + buf * 25600;
        #pragma unroll
        for (int it = 0; it < 5; it++) {
            int idx = t + it * 256;
            const __half* gp;
            uint32_t s;
            if (idx < 512) {
                int row = idx >> 2, seg = idx & 3;
                gp = g_c16 + (size_t)(m0 + row) * CD + k0 + seg * 8;
                s = dst + row * 80 + seg * 16;
            } else {
                int j = idx - 512, row = j >> 2, seg = j & 3;
                int g = row >> 6, rg = row & 63;
                gp = g_Wout16 + (size_t)(g * HID + n0 + rg) * CD + k0 + seg * 8;
                s = dst + 10240 + g * 5120 + rg * 80 + seg * 16;
            }
            CPA16(s, gp);
        }
        CPC();
    };

    const int NS = CD / 32;  // 8
    load_stage(0, 0); load_stage(1, 1);
    for (int i = 0; i < NS; i++) {
        if (i + 2 < NS) load_stage(i + 2, (i + 2) & 3); else CPC();
        CPW(2);
        __syncthreads();
        uint32_t As = sb + (i & 3) * 25600, Bs = As + 10240;
        #pragma unroll
        for (int kk = 0; kk < 32; kk += 16) {
            uint32_t ah[4][4];
            uint32_t aoff = As + wm * 5120 + (lane & 15) * 80 + (lane >> 4) * 16 + kk * 2;
            #pragma unroll
            for (int mt = 0; mt < 4; mt++) ldsm4(ah[mt], aoff + mt * 1280);
            uint32_t boff = Bs + wn * 1280 + ((lane & 7) + ((lane >> 3) & 1) * 8) * 80
                            + (lane >> 4) * 16 + kk * 2;
            #pragma unroll
            for (int g = 0; g < 3; g++) {
                uint32_t bh[4];
                ldsm4(bh, boff + g * 5120);
                #pragma unroll
                for (int mt = 0; mt < 4; mt++) {
                    mma_f16(c[g][mt][0], ah[mt], bh[0], bh[2]);
                    mma_f16(c[g][mt][1], ah[mt], bh[1], bh[3]);
                }
            }
        }
    }

    const int gr = lane >> 2, gc = (lane & 3) * 2;
    #pragma unroll
    for (int mt = 0; mt < 4; mt++)
        #pragma unroll
        for (int half = 0; half < 2; half++) {
            int row = m0 + wm * 64 + mt * 16 + gr + half * 8;
            size_t rb = (size_t)row * HID;
            #pragma unroll
            for (int nt = 0; nt < 2; nt++) {
                int ng = n0 + wn * 16 + nt * 8 + gc;
                size_t o = rb + ng;
                float a0 = c[0][mt][nt][half*2]   + b_out[ng];
                float a1 = c[0][mt][nt][half*2+1] + b_out[ng + 1];
                float b0 = c[1][mt][nt][half*2]   + b_out[HID + ng];
                float b1 = c[1][mt][nt][half*2+1] + b_out[HID + ng + 1];
                float g0 = c[2][mt][nt][half*2]   + b_out[2 * HID + ng];
                float g1 = c[2][mt][nt][half*2+1] + b_out[2 * HID + ng + 1];
                float al0 = sigm(a0), al1 = sigm(a1);
                float be0 = fminf(fmaxf(b0, 0.f) + log1pf(expf(-fabsf(b0))), 2.0f);
                float be1 = fminf(fmaxf(b1, 0.f) + log1pf(expf(-fabsf(b1))), 2.0f);
                float gt0 = sigm(g0), gt1 = sigm(g1);
                float2 hv = *(const float2*)(h + o);
                float2 vv = *(const float2*)(v + o);
                float2 mc = *(const float2*)(mu_out + o);
                float vn0 = al0 * vv.x - be0 * (hv.x - mc.x);
                float vn1 = al1 * vv.y - be1 * (hv.y - mc.y);
                vn0 = fminf(fmaxf(vn0, -10.f), 10.f);
                vn1 = fminf(fmaxf(vn1, -10.f), 10.f);
                float2 hn = { hv.x + 0.1f * gt0 * vn0, hv.y + 0.1f * gt1 * vn1 };
                float2 vn = { vn0, vn1 };
                *(float2*)(h_next + o) = hn;
                *(float2*)(v_next + o) = vn;
            }
        }
}

// ---------------- launch ----------------
extern "C" void kernel_launch(void* const* d_in, const int* in_sizes, int n_in,
                              void* d_out, int out_size)
{
    const float* h     = (const float*)d_in[0];
    const float* v     = (const float*)d_in[1];
    const float* W_in  = (const float*)d_in[2];
    const float* b_in  = (const float*)d_in[3];
    const float* W_out = (const float*)d_in[4];
    const float* b_out = (const float*)d_in[5];
    const float* W_mu  = (const float*)d_in[6];
    const float* mu    = (const float*)d_in[7];

    float* out    = (float*)d_out;
    float* h_next = out;
    float* v_next = out + (size_t)NB * HID;
    float* mu_out = out + 2 * (size_t)NB * HID;

    cudaFuncSetAttribute(k1_mma, cudaFuncAttributeMaxDynamicSharedMemorySize, 4 * 20480);
    cudaFuncSetAttribute(k2_mma, cudaFuncAttributeMaxDynamicSharedMemorySize, 4 * 20480);
    cudaFuncSetAttribute(k3_mma, cudaFuncAttributeMaxDynamicSharedMemorySize, 4 * 25600);

    const int qa = (2 * NB * HID + HID * HID) / 4;
    k_convA<<<qa / 256, 256>>>(h, v, W_mu);
    const int qb = (CD * KC + 3 * HID * CD) / 4;
    k_convB<<<qb / 256, 256>>>(W_in, W_out);

    k1_mma<<<dim3(CD / 128,  NB / 128), 256, 4 * 20480>>>(b_in);
    k2_mma<<<dim3(HID / 128, NB / 128), 256, 4 * 20480>>>(mu, mu_out);   // 4th launch -> profiled
    k3_mma<<<dim3(HID / 64,  NB / 128), 256, 4 * 25600>>>(h, v, b_out, mu_out,
                                                          h_next, v_next);
}